// round 7
// baseline (speedup 1.0000x reference)
#include <cuda_runtime.h>
#include <cstdint>

// Model_PDE_2: N=131072, H=1024, D=2.
// tf32 mma.sync (sm_80-class) formulation:
//   per (n,h): z = x0*a+x1*b+c; t = tanh(z); values {t, tt=t^2, t3=t-t^3}
//   4 contractions as D[32pts x 8] = A[32 x 3072] * B[3072 x 8]:
//     col n=0: out = sum t*w ; n=1: gA = sum tt*wa ; n=2: gB = sum tt*wb
//     n=3: dx = sum t3*wbb (wbb = -2*w*b^2) ; n=4..7 unused (zero B)
//   K layout: triples of 24 cols, col = j*8 + c -> value_j(h = tri*8 + c)
//   g0 = C0-gA, g1 = C1-gB; pde = .5*x1^2 + g0 + .5*dx + .5*x1*g1 - (.25/3.6)*g1^2
// Output: d_out[0..N)=out, d_out[N..2N)=pde.
//
// R7: B weights via __ldg from transposed global table (L2 broadcast, 1-triple
// prefetch) instead of smem -> smem 12KB, 9 CTAs/SM; no per-triple selects.

#define HID 1024
#define TPB 128
#define NTRI (HID / 8)  // 128 triples of 8 h

__device__ float2 g_ab[HID];        // {a, b}
__device__ float g_cc[HID];         // c
__device__ float g_wt[4 * HID + 8]; // rows: w | wa | wb | wbb (+pad for prefetch overread)
__device__ float g_c01[2];

__global__ void setup_kernel(const float* __restrict__ W1,
                             const float* __restrict__ b1,
                             const float* __restrict__ w2) {
    __shared__ float redA[HID];
    __shared__ float redB[HID];
    int h = threadIdx.x;
    float a = W1[2 * h], b = W1[2 * h + 1];
    float c = b1[h], w = w2[h];
    float wa = w * a;
    float wb = w * b;
    float wbb = -2.0f * w * b * b;
    g_ab[h] = make_float2(a, b);
    g_cc[h] = c;
    g_wt[0 * HID + h] = w;
    g_wt[1 * HID + h] = wa;
    g_wt[2 * HID + h] = wb;
    g_wt[3 * HID + h] = wbb;
    if (h < 8) g_wt[4 * HID + h] = 0.0f;
    redA[h] = wa;
    redB[h] = wb;
    __syncthreads();
    for (int s = HID / 2; s > 0; s >>= 1) {
        if (h < s) {
            redA[h] += redA[h + s];
            redB[h] += redB[h + s];
        }
        __syncthreads();
    }
    if (h == 0) {
        g_c01[0] = redA[0];
        g_c01[1] = redB[0];
    }
}

__device__ __forceinline__ float tanh_fast(float z) {
    float t;
    asm("tanh.approx.f32 %0, %1;" : "=f"(t) : "f"(z));
    return t;
}

__device__ __forceinline__ void mma_tf32(float* d, float a0, float a1, float a2,
                                         float a3, float b0, float b1) {
    asm volatile(
        "mma.sync.aligned.m16n8k8.row.col.f32.tf32.tf32.f32 "
        "{%0,%1,%2,%3}, {%4,%5,%6,%7}, {%8,%9}, {%0,%1,%2,%3};"
        : "+f"(d[0]), "+f"(d[1]), "+f"(d[2]), "+f"(d[3])
        : "r"(__float_as_uint(a0)), "r"(__float_as_uint(a1)),
          "r"(__float_as_uint(a2)), "r"(__float_as_uint(a3)),
          "r"(__float_as_uint(b0)), "r"(__float_as_uint(b1)));
}

__global__ __launch_bounds__(TPB, 9) void pde_kernel(const float* __restrict__ x,
                                                     const float* __restrict__ b2,
                                                     float* __restrict__ out,
                                                     int N) {
    __shared__ float2 s_ab[HID];  // 8 KB
    __shared__ float s_cc[HID];   // 4 KB

    int tid = threadIdx.x;
    for (int i = tid; i < HID; i += TPB) {
        s_ab[i] = g_ab[i];
        s_cc[i] = g_cc[i];
    }
    __syncthreads();

    int lane = tid & 31;
    int wid = tid >> 5;
    int g = lane >> 2;   // group id = output column n, also row base
    int tig = lane & 3;  // thread-in-group = k sub-col
    int n = g;
    // Octet (j) in which this output column's B entry is nonzero:
    // n=0 (w,t): j=0 ; n=1,2 (wa,wb with tt): j=1 ; n=3 (wbb,t3): j=2
    int jn = (n == 0) ? 0 : (n <= 2) ? 1 : (n == 3) ? 2 : -1;
    bool has_b = (n < 4);
    const float* wtp = g_wt + (n & 3) * HID;

    int base_pt = blockIdx.x * TPB + wid * 32;

    // Distribute x: lane loads its own point, shuffle to fragment rows.
    float2 myx = reinterpret_cast<const float2*>(x)[base_pt + lane];
    float x0r[4], x1r[4];
#pragma unroll
    for (int i = 0; i < 4; i++) {
        x0r[i] = __shfl_sync(0xffffffffu, myx.x, g + 8 * i);
        x1r[i] = __shfl_sync(0xffffffffu, myx.y, g + 8 * i);
    }

    float acc0[4] = {0.f, 0.f, 0.f, 0.f};  // tile0: rows g, g+8
    float acc1[4] = {0.f, 0.f, 0.f, 0.f};  // tile1: rows g+16, g+24

    // Prefetch B weights for triple 0.
    float nw0 = 0.f, nw1 = 0.f;
    if (has_b) {
        nw0 = __ldg(wtp + tig);
        nw1 = __ldg(wtp + tig + 4);
    }

#pragma unroll 2
    for (int tr = 0; tr < NTRI; tr++) {
        int hb = tr * 8;
        float w0 = nw0, w1 = nw1;
        // Prefetch next triple (pad allows overread on last iteration).
        if (has_b) {
            nw0 = __ldg(wtp + hb + 8 + tig);
            nw1 = __ldg(wtp + hb + 12 + tig);
        }

        int h0 = hb + tig;
        int h1 = h0 + 4;
        float2 ab0 = s_ab[h0];
        float2 ab1 = s_ab[h1];
        float cc0 = s_cc[h0];
        float cc1 = s_cc[h1];

        float v[3][4][2];
#pragma unroll
        for (int r = 0; r < 4; r++) {
            float z0 = __fmaf_rn(x1r[r], ab0.y, __fmaf_rn(x0r[r], ab0.x, cc0));
            float t0 = tanh_fast(z0);
            float tt0 = t0 * t0;
            float t30 = __fmaf_rn(-t0, tt0, t0);
            v[0][r][0] = t0;
            v[1][r][0] = tt0;
            v[2][r][0] = t30;
            float z1 = __fmaf_rn(x1r[r], ab1.y, __fmaf_rn(x0r[r], ab1.x, cc1));
            float t1 = tanh_fast(z1);
            float tt1 = t1 * t1;
            float t31 = __fmaf_rn(-t1, tt1, t1);
            v[0][r][1] = t1;
            v[1][r][1] = tt1;
            v[2][r][1] = t31;
        }
#pragma unroll
        for (int j = 0; j < 3; j++) {
            float b0 = (j == jn) ? w0 : 0.f;
            float b1 = (j == jn) ? w1 : 0.f;
            mma_tf32(acc0, v[j][0][0], v[j][1][0], v[j][0][1], v[j][1][1], b0, b1);
            mma_tf32(acc1, v[j][2][0], v[j][3][0], v[j][2][1], v[j][3][1], b0, b1);
        }
    }

    // Epilogue: thread (g, tig=0) holds cols 0,1 = {out, gA} for rows g(+8,+16,+24);
    // tig=1 holds cols 2,3 = {gB, dx}. Pull gB/dx over with shuffles.
    float sb00 = __shfl_down_sync(0xffffffffu, acc0[0], 1);
    float sb01 = __shfl_down_sync(0xffffffffu, acc0[1], 1);
    float sb02 = __shfl_down_sync(0xffffffffu, acc0[2], 1);
    float sb03 = __shfl_down_sync(0xffffffffu, acc0[3], 1);
    float sb10 = __shfl_down_sync(0xffffffffu, acc1[0], 1);
    float sb11 = __shfl_down_sync(0xffffffffu, acc1[1], 1);
    float sb12 = __shfl_down_sync(0xffffffffu, acc1[2], 1);
    float sb13 = __shfl_down_sync(0xffffffffu, acc1[3], 1);

    if (tig == 0) {
        float C0 = g_c01[0];
        float C1 = g_c01[1];
        float bz = b2[0];

        float ov[4], gA[4], gB[4], dx[4];
        ov[0] = acc0[0]; gA[0] = acc0[1]; gB[0] = sb00; dx[0] = sb01;
        ov[1] = acc0[2]; gA[1] = acc0[3]; gB[1] = sb02; dx[1] = sb03;
        ov[2] = acc1[0]; gA[2] = acc1[1]; gB[2] = sb10; dx[2] = sb11;
        ov[3] = acc1[2]; gA[3] = acc1[3]; gB[3] = sb12; dx[3] = sb13;

#pragma unroll
        for (int r = 0; r < 4; r++) {
            int p = base_pt + g + 8 * r;
            float g0 = C0 - gA[r];
            float g1 = C1 - gB[r];
            float xx1 = x1r[r];
            float pde = __fmaf_rn(0.5f * xx1, xx1, g0);
            pde = __fmaf_rn(0.5f, dx[r], pde);
            pde = __fmaf_rn(0.5f * xx1, g1, pde);
            pde = __fmaf_rn(-0.069444444444444444f * g1, g1, pde);
            out[p] = ov[r] + bz;
            out[N + p] = pde;
        }
    }
}

extern "C" void kernel_launch(void* const* d_in, const int* in_sizes, int n_in,
                              void* d_out, int out_size) {
    const float* x = (const float*)d_in[0];
    const float* W1 = (const float*)d_in[1];
    const float* b1 = (const float*)d_in[2];
    const float* w2 = (const float*)d_in[3];
    const float* b2 = (const float*)d_in[4];
    int N = in_sizes[0] / 2;

    setup_kernel<<<1, HID>>>(W1, b1, w2);
    pde_kernel<<<N / TPB, TPB>>>(x, b2, (float*)d_out, N);
}

// round 9
// speedup vs baseline: 1.0134x; 1.0134x over previous
#include <cuda_runtime.h>
#include <cstdint>

// Model_PDE_2: N=131072, H=1024, D=2.
// tf32 mma.sync (sm_80-class) formulation:
//   per (n,h): z = x0*a+x1*b+c; t = tanh(z); values {t, tt=t^2, t3=t-t^3}
//   4 contractions as D[32pts x 8] = A[32 x 3072] * B[3072 x 8]:
//     col n=0: out = sum t*w ; n=1: gA = sum tt*wa ; n=2: gB = sum tt*wb
//     n=3: dx = sum t3*wbb (wbb = -2*w*b^2) ; n=4..7 unused (zero B)
//   K layout: triples of 24 cols, col = j*8 + c -> value_j(h = tri*8 + c)
//   g0 = C0-gA, g1 = C1-gB; pde = .5*x1^2 + g0 + .5*dx + .5*x1*g1 - (.25/3.6)*g1^2
// Output: d_out[0..N)=out, d_out[N..2N)=pde.
//
// R9 (= R7 resubmit after infra failure): B weights via __ldg from transposed
// global table (L2 broadcast, 1-triple prefetch) instead of smem -> smem 12KB,
// 9 CTAs/SM target; select-free B gating.

#define HID 1024
#define TPB 128
#define NTRI (HID / 8)  // 128 triples of 8 h

__device__ float2 g_ab[HID];        // {a, b}
__device__ float g_cc[HID];         // c
__device__ float g_wt[4 * HID + 8]; // rows: w | wa | wb | wbb (+pad for prefetch overread)
__device__ float g_c01[2];

__global__ void setup_kernel(const float* __restrict__ W1,
                             const float* __restrict__ b1,
                             const float* __restrict__ w2) {
    __shared__ float redA[HID];
    __shared__ float redB[HID];
    int h = threadIdx.x;
    float a = W1[2 * h], b = W1[2 * h + 1];
    float c = b1[h], w = w2[h];
    float wa = w * a;
    float wb = w * b;
    float wbb = -2.0f * w * b * b;
    g_ab[h] = make_float2(a, b);
    g_cc[h] = c;
    g_wt[0 * HID + h] = w;
    g_wt[1 * HID + h] = wa;
    g_wt[2 * HID + h] = wb;
    g_wt[3 * HID + h] = wbb;
    if (h < 8) g_wt[4 * HID + h] = 0.0f;
    redA[h] = wa;
    redB[h] = wb;
    __syncthreads();
    for (int s = HID / 2; s > 0; s >>= 1) {
        if (h < s) {
            redA[h] += redA[h + s];
            redB[h] += redB[h + s];
        }
        __syncthreads();
    }
    if (h == 0) {
        g_c01[0] = redA[0];
        g_c01[1] = redB[0];
    }
}

__device__ __forceinline__ float tanh_fast(float z) {
    float t;
    asm("tanh.approx.f32 %0, %1;" : "=f"(t) : "f"(z));
    return t;
}

__device__ __forceinline__ void mma_tf32(float* d, float a0, float a1, float a2,
                                         float a3, float b0, float b1) {
    asm volatile(
        "mma.sync.aligned.m16n8k8.row.col.f32.tf32.tf32.f32 "
        "{%0,%1,%2,%3}, {%4,%5,%6,%7}, {%8,%9}, {%0,%1,%2,%3};"
        : "+f"(d[0]), "+f"(d[1]), "+f"(d[2]), "+f"(d[3])
        : "r"(__float_as_uint(a0)), "r"(__float_as_uint(a1)),
          "r"(__float_as_uint(a2)), "r"(__float_as_uint(a3)),
          "r"(__float_as_uint(b0)), "r"(__float_as_uint(b1)));
}

__global__ __launch_bounds__(TPB, 9) void pde_kernel(const float* __restrict__ x,
                                                     const float* __restrict__ b2,
                                                     float* __restrict__ out,
                                                     int N) {
    __shared__ float2 s_ab[HID];  // 8 KB
    __shared__ float s_cc[HID];   // 4 KB

    int tid = threadIdx.x;
    for (int i = tid; i < HID; i += TPB) {
        s_ab[i] = g_ab[i];
        s_cc[i] = g_cc[i];
    }
    __syncthreads();

    int lane = tid & 31;
    int wid = tid >> 5;
    int g = lane >> 2;   // group id = output column n, also row base
    int tig = lane & 3;  // thread-in-group = k sub-col
    int n = g;
    // Octet (j) in which this output column's B entry is nonzero:
    // n=0 (w,t): j=0 ; n=1,2 (wa,wb with tt): j=1 ; n=3 (wbb,t3): j=2
    int jn = (n == 0) ? 0 : (n <= 2) ? 1 : (n == 3) ? 2 : -1;
    bool has_b = (n < 4);
    const float* wtp = g_wt + (n & 3) * HID;

    int base_pt = blockIdx.x * TPB + wid * 32;

    // Distribute x: lane loads its own point, shuffle to fragment rows.
    float2 myx = reinterpret_cast<const float2*>(x)[base_pt + lane];
    float x0r[4], x1r[4];
#pragma unroll
    for (int i = 0; i < 4; i++) {
        x0r[i] = __shfl_sync(0xffffffffu, myx.x, g + 8 * i);
        x1r[i] = __shfl_sync(0xffffffffu, myx.y, g + 8 * i);
    }

    float acc0[4] = {0.f, 0.f, 0.f, 0.f};  // tile0: rows g, g+8
    float acc1[4] = {0.f, 0.f, 0.f, 0.f};  // tile1: rows g+16, g+24

    // Prefetch B weights for triple 0.
    float nw0 = 0.f, nw1 = 0.f;
    if (has_b) {
        nw0 = __ldg(wtp + tig);
        nw1 = __ldg(wtp + tig + 4);
    }

#pragma unroll 2
    for (int tr = 0; tr < NTRI; tr++) {
        int hb = tr * 8;
        float w0 = nw0, w1 = nw1;
        // Prefetch next triple (pad allows overread on last iteration).
        if (has_b) {
            nw0 = __ldg(wtp + hb + 8 + tig);
            nw1 = __ldg(wtp + hb + 12 + tig);
        }

        int h0 = hb + tig;
        int h1 = h0 + 4;
        float2 ab0 = s_ab[h0];
        float2 ab1 = s_ab[h1];
        float cc0 = s_cc[h0];
        float cc1 = s_cc[h1];

        float v[3][4][2];
#pragma unroll
        for (int r = 0; r < 4; r++) {
            float z0 = __fmaf_rn(x1r[r], ab0.y, __fmaf_rn(x0r[r], ab0.x, cc0));
            float t0 = tanh_fast(z0);
            float tt0 = t0 * t0;
            float t30 = __fmaf_rn(-t0, tt0, t0);
            v[0][r][0] = t0;
            v[1][r][0] = tt0;
            v[2][r][0] = t30;
            float z1 = __fmaf_rn(x1r[r], ab1.y, __fmaf_rn(x0r[r], ab1.x, cc1));
            float t1 = tanh_fast(z1);
            float tt1 = t1 * t1;
            float t31 = __fmaf_rn(-t1, tt1, t1);
            v[0][r][1] = t1;
            v[1][r][1] = tt1;
            v[2][r][1] = t31;
        }
#pragma unroll
        for (int j = 0; j < 3; j++) {
            float b0 = (j == jn) ? w0 : 0.f;
            float b1 = (j == jn) ? w1 : 0.f;
            mma_tf32(acc0, v[j][0][0], v[j][1][0], v[j][0][1], v[j][1][1], b0, b1);
            mma_tf32(acc1, v[j][2][0], v[j][3][0], v[j][2][1], v[j][3][1], b0, b1);
        }
    }

    // Epilogue: thread (g, tig=0) holds cols 0,1 = {out, gA} for rows g(+8,+16,+24);
    // tig=1 holds cols 2,3 = {gB, dx}. Pull gB/dx over with shuffles.
    float sb00 = __shfl_down_sync(0xffffffffu, acc0[0], 1);
    float sb01 = __shfl_down_sync(0xffffffffu, acc0[1], 1);
    float sb02 = __shfl_down_sync(0xffffffffu, acc0[2], 1);
    float sb03 = __shfl_down_sync(0xffffffffu, acc0[3], 1);
    float sb10 = __shfl_down_sync(0xffffffffu, acc1[0], 1);
    float sb11 = __shfl_down_sync(0xffffffffu, acc1[1], 1);
    float sb12 = __shfl_down_sync(0xffffffffu, acc1[2], 1);
    float sb13 = __shfl_down_sync(0xffffffffu, acc1[3], 1);

    if (tig == 0) {
        float C0 = g_c01[0];
        float C1 = g_c01[1];
        float bz = b2[0];

        float ov[4], gA[4], gB[4], dx[4];
        ov[0] = acc0[0]; gA[0] = acc0[1]; gB[0] = sb00; dx[0] = sb01;
        ov[1] = acc0[2]; gA[1] = acc0[3]; gB[1] = sb02; dx[1] = sb03;
        ov[2] = acc1[0]; gA[2] = acc1[1]; gB[2] = sb10; dx[2] = sb11;
        ov[3] = acc1[2]; gA[3] = acc1[3]; gB[3] = sb12; dx[3] = sb13;

#pragma unroll
        for (int r = 0; r < 4; r++) {
            int p = base_pt + g + 8 * r;
            float g0 = C0 - gA[r];
            float g1 = C1 - gB[r];
            float xx1 = x1r[r];
            float pde = __fmaf_rn(0.5f * xx1, xx1, g0);
            pde = __fmaf_rn(0.5f, dx[r], pde);
            pde = __fmaf_rn(0.5f * xx1, g1, pde);
            pde = __fmaf_rn(-0.069444444444444444f * g1, g1, pde);
            out[p] = ov[r] + bz;
            out[N + p] = pde;
        }
    }
}

extern "C" void kernel_launch(void* const* d_in, const int* in_sizes, int n_in,
                              void* d_out, int out_size) {
    const float* x = (const float*)d_in[0];
    const float* W1 = (const float*)d_in[1];
    const float* b1 = (const float*)d_in[2];
    const float* w2 = (const float*)d_in[3];
    const float* b2 = (const float*)d_in[4];
    int N = in_sizes[0] / 2;

    setup_kernel<<<1, HID>>>(W1, b1, w2);
    pde_kernel<<<N / TPB, TPB>>>(x, b2, (float*)d_out, N);
}

// round 10
// speedup vs baseline: 1.0496x; 1.0357x over previous
#include <cuda_runtime.h>
#include <cstdint>

// Model_PDE_2: N=131072, H=1024, D=2.  tf32 mma.sync formulation, R10:
// CTA-level H-split. CTA (ptile, half) computes partial contractions of
// 128 points against 512 hidden units using 14.5KB smem tables -> ~10 CTAs/SM.
// Partials go to global scratch; epilogue kernel folds halves + computes pde.
//
//   per (n,h): z = x0*a+x1*b+c; t = tanh(z); values {t, tt, t3=t-t^3}
//   D[32pts x 8] += A[32 x 24·tri] * B sparse:
//     col0: sum t*w ; col1: sum tt*wa ; col2: sum tt*wb ; col3: sum t3*wbb
//   g0 = C0-gA, g1 = C1-gB; pde = .5*x1^2+g0+.5*dx+.5*x1*g1-(.25/3.6)*g1^2
// Output: d_out[0..N)=out, d_out[N..2N)=pde.

#define HID 1024
#define HHALF 512
#define TPB 128
#define NTRI_H (HHALF / 8)  // 64 triples per half
#define WT_STRIDE 520       // rows offset by 8 banks -> conflict-free
#define NMAX 131072

__device__ float2 g_ab[HID];   // {a, b}
__device__ float g_cc[HID];    // c
__device__ float4 g_wv[HID];   // {w, wa, wb, wbb}
__device__ float g_c01[2];
__device__ float2 g_pA[2 * NMAX];  // per-half partials {out, gA}
__device__ float2 g_pB[2 * NMAX];  // per-half partials {gB, dx}

__global__ void setup_kernel(const float* __restrict__ W1,
                             const float* __restrict__ b1,
                             const float* __restrict__ w2) {
    __shared__ float redA[HID];
    __shared__ float redB[HID];
    int h = threadIdx.x;
    float a = W1[2 * h], b = W1[2 * h + 1];
    float c = b1[h], w = w2[h];
    float wa = w * a;
    float wb = w * b;
    float wbb = -2.0f * w * b * b;
    g_ab[h] = make_float2(a, b);
    g_cc[h] = c;
    g_wv[h] = make_float4(w, wa, wb, wbb);
    redA[h] = wa;
    redB[h] = wb;
    __syncthreads();
    for (int s = HID / 2; s > 0; s >>= 1) {
        if (h < s) {
            redA[h] += redA[h + s];
            redB[h] += redB[h + s];
        }
        __syncthreads();
    }
    if (h == 0) {
        g_c01[0] = redA[0];
        g_c01[1] = redB[0];
    }
}

__device__ __forceinline__ float tanh_fast(float z) {
    float t;
    asm("tanh.approx.f32 %0, %1;" : "=f"(t) : "f"(z));
    return t;
}

__device__ __forceinline__ void mma_tf32(float* d, float a0, float a1, float a2,
                                         float a3, float b0, float b1) {
    asm volatile(
        "mma.sync.aligned.m16n8k8.row.col.f32.tf32.tf32.f32 "
        "{%0,%1,%2,%3}, {%4,%5,%6,%7}, {%8,%9}, {%0,%1,%2,%3};"
        : "+f"(d[0]), "+f"(d[1]), "+f"(d[2]), "+f"(d[3])
        : "r"(__float_as_uint(a0)), "r"(__float_as_uint(a1)),
          "r"(__float_as_uint(a2)), "r"(__float_as_uint(a3)),
          "r"(__float_as_uint(b0)), "r"(__float_as_uint(b1)));
}

__global__ __launch_bounds__(TPB) void pde_main(const float* __restrict__ x,
                                                int N) {
    __shared__ float2 s_ab[HHALF];          // 4 KB
    __shared__ float s_cc[HHALF];           // 2 KB
    __shared__ float s_wt[4 * WT_STRIDE];   // 8.3 KB

    int tid = threadIdx.x;
    int half = blockIdx.x & 1;
    int ptile = blockIdx.x >> 1;
    int hoff = half * HHALF;

    for (int i = tid; i < HHALF; i += TPB) {
        s_ab[i] = g_ab[hoff + i];
        s_cc[i] = g_cc[hoff + i];
        float4 wv = g_wv[hoff + i];
        s_wt[0 * WT_STRIDE + i] = wv.x;
        s_wt[1 * WT_STRIDE + i] = wv.y;
        s_wt[2 * WT_STRIDE + i] = wv.z;
        s_wt[3 * WT_STRIDE + i] = wv.w;
    }
    __syncthreads();

    int lane = tid & 31;
    int wid = tid >> 5;
    int g = lane >> 2;   // group id = output column n, also row base
    int tig = lane & 3;  // thread-in-group = k sub-col
    int n = g;
    // Octet in which this column's B entry is nonzero:
    // n=0 (w,t): j=0 ; n=1,2 (wa,wb with tt): j=1 ; n=3 (wbb,t3): j=2
    int jn = (n == 0) ? 0 : (n <= 2) ? 1 : (n == 3) ? 2 : -1;
    bool has_b = (n < 4);
    const float* wtp = s_wt + (n & 3) * WT_STRIDE;

    int base_pt = ptile * TPB + wid * 32;

    float2 myx = reinterpret_cast<const float2*>(x)[base_pt + lane];
    float x0r[4], x1r[4];
#pragma unroll
    for (int i = 0; i < 4; i++) {
        x0r[i] = __shfl_sync(0xffffffffu, myx.x, g + 8 * i);
        x1r[i] = __shfl_sync(0xffffffffu, myx.y, g + 8 * i);
    }

    float acc0[4] = {0.f, 0.f, 0.f, 0.f};  // rows g, g+8
    float acc1[4] = {0.f, 0.f, 0.f, 0.f};  // rows g+16, g+24

#pragma unroll 2
    for (int tr = 0; tr < NTRI_H; tr++) {
        int h0 = tr * 8 + tig;
        int h1 = h0 + 4;
        float2 ab0 = s_ab[h0];
        float2 ab1 = s_ab[h1];
        float cc0 = s_cc[h0];
        float cc1 = s_cc[h1];
        float w0 = 0.f, w1 = 0.f;
        if (has_b) {
            w0 = wtp[h0];
            w1 = wtp[h1];
        }

        // Stage 1: t values -> mma octet 0
        float t[4][2];
#pragma unroll
        for (int r = 0; r < 4; r++) {
            float z0 = __fmaf_rn(x1r[r], ab0.y, __fmaf_rn(x0r[r], ab0.x, cc0));
            t[r][0] = tanh_fast(z0);
            float z1 = __fmaf_rn(x1r[r], ab1.y, __fmaf_rn(x0r[r], ab1.x, cc1));
            t[r][1] = tanh_fast(z1);
        }
        {
            float b0 = (jn == 0) ? w0 : 0.f;
            float b1 = (jn == 0) ? w1 : 0.f;
            mma_tf32(acc0, t[0][0], t[1][0], t[0][1], t[1][1], b0, b1);
            mma_tf32(acc1, t[2][0], t[3][0], t[2][1], t[3][1], b0, b1);
        }
        // Stage 2: tt = t*t -> mma octet 1
        float tt[4][2];
#pragma unroll
        for (int r = 0; r < 4; r++) {
            tt[r][0] = t[r][0] * t[r][0];
            tt[r][1] = t[r][1] * t[r][1];
        }
        {
            float b0 = (jn == 1) ? w0 : 0.f;
            float b1 = (jn == 1) ? w1 : 0.f;
            mma_tf32(acc0, tt[0][0], tt[1][0], tt[0][1], tt[1][1], b0, b1);
            mma_tf32(acc1, tt[2][0], tt[3][0], tt[2][1], tt[3][1], b0, b1);
        }
        // Stage 3: t3 = t - t^3 (in place) -> mma octet 2
#pragma unroll
        for (int r = 0; r < 4; r++) {
            t[r][0] = __fmaf_rn(-t[r][0], tt[r][0], t[r][0]);
            t[r][1] = __fmaf_rn(-t[r][1], tt[r][1], t[r][1]);
        }
        {
            float b0 = (jn == 2) ? w0 : 0.f;
            float b1 = (jn == 2) ? w1 : 0.f;
            mma_tf32(acc0, t[0][0], t[1][0], t[0][1], t[1][1], b0, b1);
            mma_tf32(acc1, t[2][0], t[3][0], t[2][1], t[3][1], b0, b1);
        }
    }

    // Partial store: tig0 holds cols {0,1} = {out, gA}; tig1 holds {2,3} = {gB, dx}.
    // Rows: acc0 -> g, g+8 ; acc1 -> g+16, g+24.
    int sbase = half * NMAX + base_pt + g;
    if (tig == 0) {
        g_pA[sbase + 0] = make_float2(acc0[0], acc0[1]);
        g_pA[sbase + 8] = make_float2(acc0[2], acc0[3]);
        g_pA[sbase + 16] = make_float2(acc1[0], acc1[1]);
        g_pA[sbase + 24] = make_float2(acc1[2], acc1[3]);
    } else if (tig == 1) {
        g_pB[sbase + 0] = make_float2(acc0[0], acc0[1]);
        g_pB[sbase + 8] = make_float2(acc0[2], acc0[3]);
        g_pB[sbase + 16] = make_float2(acc1[0], acc1[1]);
        g_pB[sbase + 24] = make_float2(acc1[2], acc1[3]);
    }
}

__global__ __launch_bounds__(256) void pde_epilogue(const float* __restrict__ x,
                                                    const float* __restrict__ b2,
                                                    float* __restrict__ out,
                                                    int N) {
    int p = blockIdx.x * 256 + threadIdx.x;
    if (p >= N) return;

    float2 a0 = g_pA[p];
    float2 a1 = g_pA[NMAX + p];
    float2 bb0 = g_pB[p];
    float2 bb1 = g_pB[NMAX + p];
    float2 xv = reinterpret_cast<const float2*>(x)[p];
    float x1 = xv.y;

    float ov = a0.x + a1.x;
    float gA = a0.y + a1.y;
    float gB = bb0.x + bb1.x;
    float dx = bb0.y + bb1.y;

    float g0 = g_c01[0] - gA;
    float g1 = g_c01[1] - gB;

    float pde = __fmaf_rn(0.5f * x1, x1, g0);
    pde = __fmaf_rn(0.5f, dx, pde);
    pde = __fmaf_rn(0.5f * x1, g1, pde);
    pde = __fmaf_rn(-0.069444444444444444f * g1, g1, pde);

    out[p] = ov + b2[0];
    out[N + p] = pde;
}

extern "C" void kernel_launch(void* const* d_in, const int* in_sizes, int n_in,
                              void* d_out, int out_size) {
    const float* x = (const float*)d_in[0];
    const float* W1 = (const float*)d_in[1];
    const float* b1 = (const float*)d_in[2];
    const float* w2 = (const float*)d_in[3];
    const float* b2 = (const float*)d_in[4];
    int N = in_sizes[0] / 2;

    setup_kernel<<<1, HID>>>(W1, b1, w2);
    pde_main<<<(N / TPB) * 2, TPB>>>(x, N);
    pde_epilogue<<<(N + 255) / 256, 256>>>(x, b2, (float*)d_out, N);
}

// round 11
// speedup vs baseline: 1.1015x; 1.0495x over previous
#include <cuda_runtime.h>
#include <cstdint>

// Model_PDE_2: N=131072, H=1024, D=2.  tf32 mma.sync, R11:
// - H-split: CTA (ptile, half) does 128 points x 512 h (14.5KB smem, high occ)
// - no setup kernel: derived weights computed inline while staging smem;
//   C0/C1 eliminated via u = 1 - t^2 accumulated directly.
//
//   per (n,h): z = x0*a+x1*b+c; t = tanh(z); u = 1-t^2; t3 = t*u
//   D[32pts x 8] += A * B sparse:
//     col0: out = sum t*w ; col1: g0 = sum u*wa ; col2: g1 = sum u*wb
//     col3: dx = sum t3*wbb   (wbb = -2*w*b^2)
//   pde = .5*x1^2 + g0 + .5*dx + .5*x1*g1 - (.25/3.6)*g1^2
// Output: d_out[0..N)=out, d_out[N..2N)=pde.

#define HID 1024
#define HHALF 512
#define TPB 128
#define NTRI_H (HHALF / 8)  // 64 triples per half
#define WT_STRIDE 520       // rows offset by 8 banks -> conflict-free
#define NMAX 131072

__device__ float2 g_pA[2 * NMAX];  // per-half partials {out, g0}
__device__ float2 g_pB[2 * NMAX];  // per-half partials {g1, dx}

__device__ __forceinline__ float tanh_fast(float z) {
    float t;
    asm("tanh.approx.f32 %0, %1;" : "=f"(t) : "f"(z));
    return t;
}

__device__ __forceinline__ void mma_tf32(float* d, float a0, float a1, float a2,
                                         float a3, float b0, float b1) {
    asm volatile(
        "mma.sync.aligned.m16n8k8.row.col.f32.tf32.tf32.f32 "
        "{%0,%1,%2,%3}, {%4,%5,%6,%7}, {%8,%9}, {%0,%1,%2,%3};"
        : "+f"(d[0]), "+f"(d[1]), "+f"(d[2]), "+f"(d[3])
        : "r"(__float_as_uint(a0)), "r"(__float_as_uint(a1)),
          "r"(__float_as_uint(a2)), "r"(__float_as_uint(a3)),
          "r"(__float_as_uint(b0)), "r"(__float_as_uint(b1)));
}

__global__ __launch_bounds__(TPB) void pde_main(const float* __restrict__ x,
                                                const float* __restrict__ W1,
                                                const float* __restrict__ b1,
                                                const float* __restrict__ w2,
                                                int N) {
    __shared__ float2 s_ab[HHALF];          // 4 KB
    __shared__ float s_cc[HHALF];           // 2 KB
    __shared__ float s_wt[4 * WT_STRIDE];   // 8.3 KB

    int tid = threadIdx.x;
    int half = blockIdx.x & 1;
    int ptile = blockIdx.x >> 1;
    int hoff = half * HHALF;

    // Stage + derive weights inline (W1/b1/w2 slice is L2-resident).
    for (int i = tid; i < HHALF; i += TPB) {
        int h = hoff + i;
        float2 ab = reinterpret_cast<const float2*>(W1)[h];
        float c = b1[h];
        float w = w2[h];
        s_ab[i] = ab;
        s_cc[i] = c;
        s_wt[0 * WT_STRIDE + i] = w;                       // w
        s_wt[1 * WT_STRIDE + i] = w * ab.x;                // wa
        s_wt[2 * WT_STRIDE + i] = w * ab.y;                // wb
        s_wt[3 * WT_STRIDE + i] = -2.0f * w * ab.y * ab.y; // wbb
    }
    __syncthreads();

    int lane = tid & 31;
    int wid = tid >> 5;
    int g = lane >> 2;   // group id = output column n, also row base
    int tig = lane & 3;  // thread-in-group = k sub-col
    int n = g;
    // Octet in which this column's B entry is nonzero:
    // n=0 (w, t): j=0 ; n=1,2 (wa,wb with u): j=1 ; n=3 (wbb, t3): j=2
    int jn = (n == 0) ? 0 : (n <= 2) ? 1 : (n == 3) ? 2 : -1;
    bool has_b = (n < 4);
    const float* wtp = s_wt + (n & 3) * WT_STRIDE;

    int base_pt = ptile * TPB + wid * 32;

    float2 myx = reinterpret_cast<const float2*>(x)[base_pt + lane];
    float x0r[4], x1r[4];
#pragma unroll
    for (int i = 0; i < 4; i++) {
        x0r[i] = __shfl_sync(0xffffffffu, myx.x, g + 8 * i);
        x1r[i] = __shfl_sync(0xffffffffu, myx.y, g + 8 * i);
    }

    float acc0[4] = {0.f, 0.f, 0.f, 0.f};  // rows g, g+8
    float acc1[4] = {0.f, 0.f, 0.f, 0.f};  // rows g+16, g+24

#pragma unroll 2
    for (int tr = 0; tr < NTRI_H; tr++) {
        int h0 = tr * 8 + tig;
        int h1 = h0 + 4;
        float2 ab0 = s_ab[h0];
        float2 ab1 = s_ab[h1];
        float cc0 = s_cc[h0];
        float cc1 = s_cc[h1];
        float w0 = 0.f, w1 = 0.f;
        if (has_b) {
            w0 = wtp[h0];
            w1 = wtp[h1];
        }

        // Stage 1: t -> mma octet 0
        float t[4][2];
#pragma unroll
        for (int r = 0; r < 4; r++) {
            float z0 = __fmaf_rn(x1r[r], ab0.y, __fmaf_rn(x0r[r], ab0.x, cc0));
            t[r][0] = tanh_fast(z0);
            float z1 = __fmaf_rn(x1r[r], ab1.y, __fmaf_rn(x0r[r], ab1.x, cc1));
            t[r][1] = tanh_fast(z1);
        }
        {
            float b0 = (jn == 0) ? w0 : 0.f;
            float b1 = (jn == 0) ? w1 : 0.f;
            mma_tf32(acc0, t[0][0], t[1][0], t[0][1], t[1][1], b0, b1);
            mma_tf32(acc1, t[2][0], t[3][0], t[2][1], t[3][1], b0, b1);
        }
        // Stage 2: u = 1 - t^2 -> mma octet 1
        float u[4][2];
#pragma unroll
        for (int r = 0; r < 4; r++) {
            u[r][0] = __fmaf_rn(-t[r][0], t[r][0], 1.0f);
            u[r][1] = __fmaf_rn(-t[r][1], t[r][1], 1.0f);
        }
        {
            float b0 = (jn == 1) ? w0 : 0.f;
            float b1 = (jn == 1) ? w1 : 0.f;
            mma_tf32(acc0, u[0][0], u[1][0], u[0][1], u[1][1], b0, b1);
            mma_tf32(acc1, u[2][0], u[3][0], u[2][1], u[3][1], b0, b1);
        }
        // Stage 3: t3 = t * u (in place) -> mma octet 2
#pragma unroll
        for (int r = 0; r < 4; r++) {
            t[r][0] = t[r][0] * u[r][0];
            t[r][1] = t[r][1] * u[r][1];
        }
        {
            float b0 = (jn == 2) ? w0 : 0.f;
            float b1 = (jn == 2) ? w1 : 0.f;
            mma_tf32(acc0, t[0][0], t[1][0], t[0][1], t[1][1], b0, b1);
            mma_tf32(acc1, t[2][0], t[3][0], t[2][1], t[3][1], b0, b1);
        }
    }

    // Partial store: tig0 holds cols {0,1} = {out, g0}; tig1 holds {2,3} = {g1, dx}.
    int sbase = half * NMAX + base_pt + g;
    if (tig == 0) {
        g_pA[sbase + 0] = make_float2(acc0[0], acc0[1]);
        g_pA[sbase + 8] = make_float2(acc0[2], acc0[3]);
        g_pA[sbase + 16] = make_float2(acc1[0], acc1[1]);
        g_pA[sbase + 24] = make_float2(acc1[2], acc1[3]);
    } else if (tig == 1) {
        g_pB[sbase + 0] = make_float2(acc0[0], acc0[1]);
        g_pB[sbase + 8] = make_float2(acc0[2], acc0[3]);
        g_pB[sbase + 16] = make_float2(acc1[0], acc1[1]);
        g_pB[sbase + 24] = make_float2(acc1[2], acc1[3]);
    }
}

__global__ __launch_bounds__(256) void pde_epilogue(const float* __restrict__ x,
                                                    const float* __restrict__ b2,
                                                    float* __restrict__ out,
                                                    int N) {
    int p = blockIdx.x * 256 + threadIdx.x;
    if (p >= N) return;

    float2 a0 = g_pA[p];
    float2 a1 = g_pA[NMAX + p];
    float2 bb0 = g_pB[p];
    float2 bb1 = g_pB[NMAX + p];
    float2 xv = reinterpret_cast<const float2*>(x)[p];
    float x1 = xv.y;

    float ov = a0.x + a1.x;
    float g0 = a0.y + a1.y;
    float g1 = bb0.x + bb1.x;
    float dx = bb0.y + bb1.y;

    float pde = __fmaf_rn(0.5f * x1, x1, g0);
    pde = __fmaf_rn(0.5f, dx, pde);
    pde = __fmaf_rn(0.5f * x1, g1, pde);
    pde = __fmaf_rn(-0.069444444444444444f * g1, g1, pde);

    out[p] = ov + b2[0];
    out[N + p] = pde;
}

extern "C" void kernel_launch(void* const* d_in, const int* in_sizes, int n_in,
                              void* d_out, int out_size) {
    const float* x = (const float*)d_in[0];
    const float* W1 = (const float*)d_in[1];
    const float* b1 = (const float*)d_in[2];
    const float* w2 = (const float*)d_in[3];
    const float* b2 = (const float*)d_in[4];
    int N = in_sizes[0] / 2;

    pde_main<<<(N / TPB) * 2, TPB>>>(x, W1, b1, w2, N);
    pde_epilogue<<<(N + 255) / 256, 256>>>(x, b2, (float*)d_out, N);
}